// round 6
// baseline (speedup 1.0000x reference)
#include <cuda_runtime.h>
#include <cuda_bf16.h>
#include <math.h>
#include <float.h>
#include <stdint.h>

// Problem constants
#define B_   8
#define S_   1024
#define IDIM 1024
#define ODIM 1024
#define H_   16
#define HD_  64
#define CN   3072           // K | Q | V columns in scratch
#define M_   (B_ * S_)      // 8192

// GEMM tiling
#define TM 128
#define TN 128
#define TK 32               // real-K per tile
#define NKT 32              // 1024 / 32
#define STAGE_BYTES 32768   // Ahi8K + Alo8K + Bhi8K + Blo8K
#define NSTAGE 3
#define SMEM_ALLOC (NSTAGE * STAGE_BYTES + 1024)

// Scratch
__device__ float g_C[(size_t)M_ * CN];               // K|Q|V fp32
__device__ float g_vsum[4 * B_ * ODIM];
__device__ float g_bias[CN];
__device__ __nv_bfloat16 g_Xhi[(size_t)M_ * IDIM];
__device__ __nv_bfloat16 g_Xlo[(size_t)M_ * IDIM];
__device__ __nv_bfloat16 g_Wthi[(size_t)CN * IDIM];  // W^T, [n][k] K-major
__device__ __nv_bfloat16 g_Wtlo[(size_t)CN * IDIM];

__device__ __forceinline__ uint32_t smem_u32(const void* p) {
    uint32_t a;
    asm("{ .reg .u64 t; cvta.to.shared.u64 t, %1; cvt.u32.u64 %0, t; }" : "=r"(a) : "l"(p));
    return a;
}
#define CP16(dst, src) \
    asm volatile("cp.async.cg.shared.global [%0], [%1], 16;" :: "r"(dst), "l"(src) : "memory")
#define CP_COMMIT() asm volatile("cp.async.commit_group;" ::: "memory")
#define CP_WAIT1()  asm volatile("cp.async.wait_group 1;" ::: "memory")

#define LDM4(r, addr) \
    asm volatile("ldmatrix.sync.aligned.m8n8.x4.shared.b16 {%0,%1,%2,%3}, [%4];" \
        : "=r"((r)[0]), "=r"((r)[1]), "=r"((r)[2]), "=r"((r)[3]) : "r"(addr))

#define MMA(acc, a, b0, b1) \
    asm volatile("mma.sync.aligned.m16n8k16.row.col.f32.bf16.bf16.f32 " \
        "{%0,%1,%2,%3}, {%4,%5,%6,%7}, {%8,%9}, {%0,%1,%2,%3};" \
        : "+f"((acc)[0]), "+f"((acc)[1]), "+f"((acc)[2]), "+f"((acc)[3]) \
        : "r"((a)[0]), "r"((a)[1]), "r"((a)[2]), "r"((a)[3]), "r"(b0), "r"(b1))

// ---------------------------------------------------------------------------
// xsplit: X -> bf16 hi/lo; also build combined bias
// ---------------------------------------------------------------------------
__global__ void xsplit_kernel(const float* __restrict__ X,
                              const float* __restrict__ bc, const float* __restrict__ bv)
{
    const size_t gid = (size_t)blockIdx.x * 256 + threadIdx.x;
    if (gid < CN) g_bias[gid] = (gid < 1024) ? bv[gid] : bc[gid - 1024];

    const size_t i = gid * 4;
    float4 x = *(const float4*)(X + i);
    float v[4] = { x.x, x.y, x.z, x.w };
    ushort4 uh, ul;
    unsigned short* ph = (unsigned short*)&uh;
    unsigned short* pl = (unsigned short*)&ul;
#pragma unroll
    for (int c = 0; c < 4; ++c) {
        __nv_bfloat16 h = __float2bfloat16(v[c]);
        __nv_bfloat16 l = __float2bfloat16(v[c] - __bfloat162float(h));
        ph[c] = __bfloat16_as_ushort(h);
        pl[c] = __bfloat16_as_ushort(l);
    }
    *reinterpret_cast<ushort4*>(g_Xhi + i) = uh;
    *reinterpret_cast<ushort4*>(g_Xlo + i) = ul;
}

// ---------------------------------------------------------------------------
// wtrans: W^T ([3072][1024] K-major) bf16 hi/lo.  cols 0..1023 = Wv, rest = Wc
// ---------------------------------------------------------------------------
__global__ void wtrans_kernel(const float* __restrict__ Wc, const float* __restrict__ Wv)
{
    __shared__ float tile[32][33];
    const int tx = threadIdx.x & 31;
    const int ty = threadIdx.x >> 5;
    const int nb = blockIdx.x * 32;
    const int kb = blockIdx.y * 32;

#pragma unroll
    for (int p = 0; p < 4; ++p) {
        const int k = kb + p * 8 + ty;
        const int n = nb + tx;
        float v = (n < 1024) ? Wv[(size_t)k * 1024 + n]
                             : Wc[(size_t)k * 2048 + (n - 1024)];
        tile[tx][p * 8 + ty] = v;
    }
    __syncthreads();
#pragma unroll
    for (int p = 0; p < 4; ++p) {
        const int nl = p * 8 + ty;
        float v = tile[nl][tx];
        __nv_bfloat16 h = __float2bfloat16(v);
        __nv_bfloat16 l = __float2bfloat16(v - __bfloat162float(h));
        const size_t o = (size_t)(nb + nl) * 1024 + kb + tx;
        g_Wthi[o] = h;
        g_Wtlo[o] = l;
    }
}

// ---------------------------------------------------------------------------
// HMMA split-bf16 GEMM: C[8192 x 3072] = X @ W + bias  (3-pass Markidis)
// 128x128 CTA tile, 8 warps (2m x 4n), warp tile 64x32, k-tile 32
// 3-stage cp.async ring, ONE __syncthreads per k-tile, 2 CTAs/SM.
// Loop invariant: at iter kt, pending groups = {kt, kt+1}; wait<=1 => kt done.
// load(kt+2) targets stage (kt+2)%3 == (kt-1)%3, whose readers finished
// before the barrier at the top of iter kt (>=3 stages required).
// ---------------------------------------------------------------------------
__global__ void __launch_bounds__(256, 2) mma_kernel()
{
    extern __shared__ __align__(16) char smem[];
    const uint32_t sb0 = smem_u32(smem);
    const uint32_t db  = (sb0 + 1023) & ~1023u;

    const int t  = threadIdx.x;
    const int l  = t & 31;
    const int w  = t >> 5;
    const int wm = w >> 2;          // 0..1
    const int wn = w & 3;           // 0..3
    const int n0 = blockIdx.x * TN;
    const int m0 = blockIdx.y * TM;

    // ---- cp.async stage loader ----
    const int lrow = t >> 1;               // 0..127
    const int lc0  = (t & 1) * 2;          // chunk 0 or 2
    const int lsw  = (lrow >> 1) & 3;
    auto load_stage = [&](int kt, int s) {
        const uint32_t sbase = db + s * STAGE_BYTES;
        const size_t gA = (size_t)(m0 + lrow) * 1024 + kt * TK;
        const size_t gB = (size_t)(n0 + lrow) * 1024 + kt * TK;
#pragma unroll
        for (int cc = 0; cc < 2; ++cc) {
            const int ch = lc0 + cc;
            const uint32_t so = (uint32_t)(lrow * 64 + ((ch ^ lsw) << 4));
            CP16(sbase + so,         g_Xhi  + gA + ch * 8);
            CP16(sbase + 8192 + so,  g_Xlo  + gA + ch * 8);
            CP16(sbase + 16384 + so, g_Wthi + gB + ch * 8);
            CP16(sbase + 24576 + so, g_Wtlo + gB + ch * 8);
        }
    };

    // ---- per-thread ldmatrix address invariants ----
    uint32_t offA[4], swA[4];
#pragma unroll
    for (int mt = 0; mt < 4; ++mt) {
        const int r = wm * 64 + mt * 16 + (l & 15);
        offA[mt] = (uint32_t)(r * 64);
        swA[mt]  = (uint32_t)(((r >> 1) & 3) << 4);
    }
    const uint32_t ahib = ((l >> 4) & 1) << 4;
    uint32_t offB[2], swB[2];
#pragma unroll
    for (int nt2 = 0; nt2 < 2; ++nt2) {
        const int r = wn * 32 + nt2 * 16 + (l & 7) + ((l & 16) ? 8 : 0);
        offB[nt2] = (uint32_t)(r * 64);
        swB[nt2]  = (uint32_t)(((r >> 1) & 3) << 4);
    }
    const uint32_t bhib = ((l >> 3) & 1) << 4;

    float acc[4][4][4];
#pragma unroll
    for (int mt = 0; mt < 4; ++mt)
#pragma unroll
        for (int nt = 0; nt < 4; ++nt)
#pragma unroll
            for (int c = 0; c < 4; ++c) acc[mt][nt][c] = 0.0f;

    // ---- 3-stage pipeline, one barrier per iteration ----
    load_stage(0, 0); CP_COMMIT();
    load_stage(1, 1); CP_COMMIT();

    for (int kt = 0; kt < NKT; ++kt) {
        CP_WAIT1();                 // stage kt landed (issued 2 iters ago)
        __syncthreads();

        if (kt + 2 < NKT) load_stage(kt + 2, (kt + 2) % NSTAGE);
        CP_COMMIT();                // empty group on tail keeps count invariant

        const uint32_t sbase = db + (kt % NSTAGE) * STAGE_BYTES;
#pragma unroll
        for (int ks = 0; ks < 2; ++ks) {
            const uint32_t kchA = (uint32_t)(ks * 32) + ahib;   // chunk*16
            const uint32_t kchB = (uint32_t)(ks * 32) + bhib;
            uint32_t bhi[2][4], blo[2][4], a[4][4];
#pragma unroll
            for (int nt2 = 0; nt2 < 2; ++nt2) {
                const uint32_t bd = sbase + 16384 + offB[nt2] + (kchB ^ swB[nt2]);
                LDM4(bhi[nt2], bd);
                LDM4(blo[nt2], bd + 8192);
            }
            // pass 1+2: A-hi x (B-hi, B-lo)
#pragma unroll
            for (int mt = 0; mt < 4; ++mt)
                LDM4(a[mt], sbase + offA[mt] + (kchA ^ swA[mt]));
#pragma unroll
            for (int mt = 0; mt < 4; ++mt)
#pragma unroll
                for (int nt = 0; nt < 4; ++nt) {
                    const int q = nt >> 1, hh = (nt & 1) * 2;
                    MMA(acc[mt][nt], a[mt], bhi[q][hh], bhi[q][hh + 1]);
                    MMA(acc[mt][nt], a[mt], blo[q][hh], blo[q][hh + 1]);
                }
            // pass 3: A-lo x B-hi (overwrites A frags)
#pragma unroll
            for (int mt = 0; mt < 4; ++mt)
                LDM4(a[mt], sbase + 8192 + offA[mt] + (kchA ^ swA[mt]));
#pragma unroll
            for (int mt = 0; mt < 4; ++mt)
#pragma unroll
                for (int nt = 0; nt < 4; ++nt) {
                    const int q = nt >> 1, hh = (nt & 1) * 2;
                    MMA(acc[mt][nt], a[mt], bhi[q][hh], bhi[q][hh + 1]);
                }
        }
    }

    // ---- epilogue: bias + fp32 store to g_C ----
#pragma unroll
    for (int mt = 0; mt < 4; ++mt) {
        const int r0 = m0 + wm * 64 + mt * 16 + (l >> 2);
#pragma unroll
        for (int nt = 0; nt < 4; ++nt) {
            const int col = n0 + wn * 32 + nt * 8 + (l & 3) * 2;
            const float2 bb = *(const float2*)(g_bias + col);
            float2 o;
            o.x = acc[mt][nt][0] + bb.x;
            o.y = acc[mt][nt][1] + bb.y;
            *(float2*)(g_C + (size_t)r0 * CN + col) = o;
            o.x = acc[mt][nt][2] + bb.x;
            o.y = acc[mt][nt][3] + bb.y;
            *(float2*)(g_C + (size_t)(r0 + 8) * CN + col) = o;
        }
    }
}

// ---------------------------------------------------------------------------
// Partial column sums of V (uniform fallback)
// ---------------------------------------------------------------------------
__global__ void vsum_kernel()
{
    const int col = (blockIdx.x & 7) * 128 + threadIdx.x;
    const int b   = blockIdx.x >> 3;
    const int s0  = blockIdx.y * 256;
    const float* base = g_C + (size_t)(b * S_ + s0) * CN + 2048 + col;
    float s = 0.0f;
#pragma unroll 8
    for (int k = 0; k < 256; ++k) s += base[(size_t)k * CN];
    g_vsum[blockIdx.y * (B_ * ODIM) + b * ODIM + col] = s;
}

// ---------------------------------------------------------------------------
// Local attention (one warp per row) — unchanged (passed R2/R4/R5)
// ---------------------------------------------------------------------------
__global__ void __launch_bounds__(256) attn_kernel(
    const float* __restrict__ m_feats, const int* __restrict__ mask,
    float* __restrict__ out_um, float* __restrict__ out_w)
{
    __shared__ float sk[8][64];
    __shared__ float sw[8][16];

    const int wid = threadIdx.x >> 5;
    const int l   = threadIdx.x & 31;
    const int row = blockIdx.x * 8 + wid;
    const int b   = row >> 14;
    const int h   = (row >> 10) & 15;
    const int i   = row & 1023;
    const int lo  = i - 7;

    {
        const float* kp = g_C + (size_t)(b * S_ + i) * CN + h * HD_;
        float2 kv = *(const float2*)(kp + 2 * l);
        sk[wid][2 * l]     = kv.x;
        sk[wid][2 * l + 1] = kv.y;
    }
    __syncwarp();

    float score = -FLT_MAX;
    if (l < 15) {
        const int j = lo + l;
        if (j >= 0 && j < S_ && mask[b * S_ + j] != 0) {
            const float* q = g_C + (size_t)(b * S_ + j) * CN + 1024 + h * HD_;
            float dot = 0.0f;
#pragma unroll
            for (int d = 0; d < HD_; d += 4) {
                float4 qq = *(const float4*)(q + d);
                dot += sk[wid][d]     * qq.x + sk[wid][d + 1] * qq.y
                     + sk[wid][d + 2] * qq.z + sk[wid][d + 3] * qq.w;
            }
            score = dot * 0.125f;
        }
    }

    float m = score;
#pragma unroll
    for (int o = 16; o; o >>= 1) m = fmaxf(m, __shfl_xor_sync(0xFFFFFFFFu, m, o));
    const bool uniform = (m == -FLT_MAX);

    float w = 0.0f;
    if (!uniform) {
        float e = (score != -FLT_MAX) ? expf(score - m) : 0.0f;
        float s = e;
#pragma unroll
        for (int o = 16; o; o >>= 1) s += __shfl_xor_sync(0xFFFFFFFFu, s, o);
        w = e / s;
    }
    if (l < 16) sw[wid][l] = (l < 15) ? w : 0.0f;
    __syncwarp();

    float r0 = 0.0f, r1 = 0.0f;
    if (!uniform) {
#pragma unroll
        for (int jj = 0; jj < 15; ++jj) {
            const float wv = sw[wid][jj];
            if (wv != 0.0f) {
                const float* v = g_C + (size_t)(b * S_ + lo + jj) * CN + 2048 + h * HD_;
                float2 vv = *(const float2*)(v + 2 * l);
                r0 = fmaf(wv, vv.x, r0);
                r1 = fmaf(wv, vv.y, r1);
            }
        }
    } else {
        const int c = h * HD_ + 2 * l;
        float s0 = 0.0f, s1 = 0.0f;
#pragma unroll
        for (int p = 0; p < 4; ++p) {
            s0 += g_vsum[p * (B_ * ODIM) + b * ODIM + c];
            s1 += g_vsum[p * (B_ * ODIM) + b * ODIM + c + 1];
        }
        r0 = s0 * (1.0f / 1024.0f);
        r1 = s1 * (1.0f / 1024.0f);
    }

    {
        const size_t uoff = (size_t)(b * S_ + i) * ODIM + h * HD_ + 2 * l;
        float2 mf = *(const float2*)(m_feats + uoff);
        float2 o;
        o.x = mf.x + r0;
        o.y = mf.y + r1;
        *(float2*)(out_um + uoff) = o;
    }

    {
        float* wr = out_w + (size_t)row * S_;
        const float uval = 1.0f / 1024.0f;
#pragma unroll
        for (int tt = 0; tt < 8; ++tt) {
            const int col = tt * 128 + l * 4;
            float4 o;
            if (uniform) {
                o = make_float4(uval, uval, uval, uval);
            } else {
                o.x = ((unsigned)(col     - lo) < 15u) ? sw[wid][col     - lo] : 0.0f;
                o.y = ((unsigned)(col + 1 - lo) < 15u) ? sw[wid][col + 1 - lo] : 0.0f;
                o.z = ((unsigned)(col + 2 - lo) < 15u) ? sw[wid][col + 2 - lo] : 0.0f;
                o.w = ((unsigned)(col + 3 - lo) < 15u) ? sw[wid][col + 3 - lo] : 0.0f;
            }
            *(float4*)(wr + col) = o;
        }
    }
}

// ---------------------------------------------------------------------------
extern "C" void kernel_launch(void* const* d_in, const int* in_sizes, int n_in,
                              void* d_out, int out_size)
{
    (void)in_sizes; (void)n_in; (void)out_size;
    const float* m_feats = (const float*)d_in[0];
    const int*   mask    = (const int*)  d_in[1];
    const float* Wc      = (const float*)d_in[2];
    const float* bc      = (const float*)d_in[3];
    const float* Wv      = (const float*)d_in[4];
    const float* bv      = (const float*)d_in[5];

    float* out_um = (float*)d_out;
    float* out_w  = out_um + (size_t)B_ * S_ * ODIM;

    cudaFuncSetAttribute(mma_kernel, cudaFuncAttributeMaxDynamicSharedMemorySize, SMEM_ALLOC);

    xsplit_kernel<<<(M_ * IDIM) / 1024, 256>>>(m_feats, bc, bv);
    wtrans_kernel<<<dim3(CN / 32, IDIM / 32), 256>>>(Wc, Wv);
    mma_kernel<<<dim3(CN / TN, M_ / TM), 256, SMEM_ALLOC>>>();
    vsum_kernel<<<dim3(64, 4), 128>>>();
    attn_kernel<<<(B_ * H_ * S_) / 8, 256>>>(m_feats, mask, out_um, out_w);
}

// round 8
// speedup vs baseline: 1.2296x; 1.2296x over previous
#include <cuda_runtime.h>
#include <cuda_bf16.h>
#include <math.h>
#include <float.h>
#include <stdint.h>

// Problem constants
#define B_   8
#define S_   1024
#define IDIM 1024
#define ODIM 1024
#define H_   16
#define HD_  64
#define CN   3072           // K | Q | V columns in scratch
#define M_   (B_ * S_)      // 8192

// GEMM tiling
#define TM 128
#define TN 128
#define TK 32               // K elements per tile (32 int8 bytes per row)
#define NKT 32              // 1024 / 32
#define STAGE_BYTES 16384   // A1 4K + A0 4K + B1 4K + B0 4K
#define NSTAGE 3
#define SMEM_ALLOC (NSTAGE * STAGE_BYTES + 1024)

// Quantization scales: x = SX*(a1*128 + a0), w = SW*(b1*128 + b0)
#define SX (6.0f / 16384.0f)
#define SW (0.19f / 16384.0f)
#define SX_INV (16384.0f / 6.0f)
#define SW_INV (16384.0f / 0.19f)

// Scratch
__device__ float g_C[(size_t)M_ * CN];               // K|Q|V fp32
__device__ float g_vsum[4 * B_ * ODIM];
__device__ float g_bias[CN];
__device__ uint32_t g_Xq1[(size_t)M_ * IDIM / 4];    // X hi limb (int8 packed)
__device__ uint32_t g_Xq0[(size_t)M_ * IDIM / 4];    // X lo limb
__device__ uint32_t g_Wq1[(size_t)CN * IDIM / 4];    // W^T hi limb, [n][k] K-major
__device__ uint32_t g_Wq0[(size_t)CN * IDIM / 4];    // W^T lo limb

__device__ __forceinline__ uint32_t smem_u32(const void* p) {
    uint32_t a;
    asm("{ .reg .u64 t; cvta.to.shared.u64 t, %1; cvt.u32.u64 %0, t; }" : "=r"(a) : "l"(p));
    return a;
}
#define CP16(dst, src) \
    asm volatile("cp.async.cg.shared.global [%0], [%1], 16;" :: "r"(dst), "l"(src) : "memory")
#define CP_COMMIT() asm volatile("cp.async.commit_group;" ::: "memory")
#define CP_WAIT1()  asm volatile("cp.async.wait_group 1;" ::: "memory")

#define LDM4(r, addr) \
    asm volatile("ldmatrix.sync.aligned.m8n8.x4.shared.b16 {%0,%1,%2,%3}, [%4];" \
        : "=r"((r)[0]), "=r"((r)[1]), "=r"((r)[2]), "=r"((r)[3]) : "r"(addr))

#define IMMA(acc, a, b0, b1) \
    asm volatile("mma.sync.aligned.m16n8k32.row.col.s32.s8.s8.s32 " \
        "{%0,%1,%2,%3}, {%4,%5,%6,%7}, {%8,%9}, {%0,%1,%2,%3};" \
        : "+r"((acc)[0]), "+r"((acc)[1]), "+r"((acc)[2]), "+r"((acc)[3]) \
        : "r"((a)[0]), "r"((a)[1]), "r"((a)[2]), "r"((a)[3]), "r"(b0), "r"(b1))

__device__ __forceinline__ int clamp8(int v) {
    return v < -127 ? -127 : (v > 127 ? 127 : v);
}
// quantize scaled value X into hi/lo int8 limbs (radix 128)
__device__ __forceinline__ void quant2(float X, int& hi, int& lo) {
    int a1 = __float2int_rn(X * 0.0078125f);
    a1 = clamp8(a1);
    int a0 = __float2int_rn(X) - (a1 << 7);
    lo = clamp8(a0);
    hi = a1;
}

// ---------------------------------------------------------------------------
// xq: quantize X to int8 limbs; also build combined bias
// ---------------------------------------------------------------------------
__global__ void xq_kernel(const float* __restrict__ X,
                          const float* __restrict__ bc, const float* __restrict__ bv)
{
    const size_t gid = (size_t)blockIdx.x * 256 + threadIdx.x;
    if (gid < CN) g_bias[gid] = (gid < 1024) ? bv[gid] : bc[gid - 1024];

    float4 x = *(const float4*)(X + gid * 4);
    float v[4] = { x.x, x.y, x.z, x.w };
    uint32_t p1 = 0, p0 = 0;
#pragma unroll
    for (int c = 0; c < 4; ++c) {
        int hi, lo;
        quant2(v[c] * SX_INV, hi, lo);
        p1 |= (uint32_t)(hi & 0xFF) << (c * 8);
        p0 |= (uint32_t)(lo & 0xFF) << (c * 8);
    }
    g_Xq1[gid] = p1;
    g_Xq0[gid] = p0;
}

// ---------------------------------------------------------------------------
// wq: transpose W to [3072][1024] K-major, quantize to int8 limbs
// ---------------------------------------------------------------------------
__global__ void wq_kernel(const float* __restrict__ Wc, const float* __restrict__ Wv)
{
    __shared__ float tile[32][33];
    const int t  = threadIdx.x;
    const int tx = t & 31;
    const int ty = t >> 5;            // 0..7
    const int nb = blockIdx.x * 32;
    const int kb = blockIdx.y * 32;

#pragma unroll
    for (int p = 0; p < 4; ++p) {
        const int k = kb + p * 8 + ty;
        const int n = nb + tx;
        float v = (n < 1024) ? Wv[(size_t)k * 1024 + n]
                             : Wc[(size_t)k * 2048 + (n - 1024)];
        tile[tx][p * 8 + ty] = v;
    }
    __syncthreads();

    const int nl = t >> 3;            // 0..31
    const int kg = t & 7;             // k-group of 4
    uint32_t p1 = 0, p0 = 0;
#pragma unroll
    for (int j = 0; j < 4; ++j) {
        int hi, lo;
        quant2(tile[nl][kg * 4 + j] * SW_INV, hi, lo);
        p1 |= (uint32_t)(hi & 0xFF) << (j * 8);
        p0 |= (uint32_t)(lo & 0xFF) << (j * 8);
    }
    const size_t o = ((size_t)(nb + nl) * 1024 + kb + kg * 4) >> 2;
    g_Wq1[o] = p1;
    g_Wq0[o] = p0;
}

// ---------------------------------------------------------------------------
// IMMA int8-limb GEMM: C = X @ W + bias
// C = SX*SW*(2^14 * sum(a1*b1) + 2^7 * sum(a1*b0 + a0*b1))   [a0*b0 dropped]
// 128x128 CTA tile, 8 warps (2m x 4n), warp tile 64x32, k-tile 32 (bytes)
// Smem rows = 32 B; chunk swizzle ch' = ch ^ ((row>>2)&1)  (conflict-free)
// ---------------------------------------------------------------------------
__global__ void __launch_bounds__(256) mma_kernel()
{
    extern __shared__ __align__(16) char smem[];
    const uint32_t sb0 = smem_u32(smem);
    const uint32_t db  = (sb0 + 1023) & ~1023u;

    const int t  = threadIdx.x;
    const int l  = t & 31;
    const int w  = t >> 5;
    const int wm = w >> 2;          // 0..1
    const int wn = w & 3;           // 0..3
    const int n0 = blockIdx.x * TN;
    const int m0 = blockIdx.y * TM;

    // ---- cp.async stage loader: 4 x 16B per thread ----
    const int lrow = t >> 1;               // 0..127
    const int lch  = t & 1;                // 16B chunk in 32B row
    const uint32_t lso = (uint32_t)(lrow * 32 + ((lch ^ ((lrow >> 2) & 1)) << 4));
    auto load_stage = [&](int kt, int s) {
        const uint32_t sbase = db + s * STAGE_BYTES;
        const size_t gA = (size_t)(m0 + lrow) * 1024 + kt * TK + lch * 16;
        const size_t gB = (size_t)(n0 + lrow) * 1024 + kt * TK + lch * 16;
        CP16(sbase + lso,          (const char*)g_Xq1 + gA);
        CP16(sbase + 4096 + lso,   (const char*)g_Xq0 + gA);
        CP16(sbase + 8192 + lso,   (const char*)g_Wq1 + gB);
        CP16(sbase + 12288 + lso,  (const char*)g_Wq0 + gB);
    };

    // ---- per-thread ldmatrix byte offsets (row + swizzled chunk baked in) ----
    const int lr8 = (l & 7) + ((l & 8) ? 8 : 0);   // row within 16-row tile
    const int lchm = (l >> 4) & 1;                 // chunk select
    uint32_t offA[4];
#pragma unroll
    for (int mt = 0; mt < 4; ++mt) {
        const int r = wm * 64 + mt * 16 + lr8;
        offA[mt] = (uint32_t)(r * 32 + ((lchm ^ ((r >> 2) & 1)) << 4));
    }
    uint32_t offB[2];
#pragma unroll
    for (int nt2 = 0; nt2 < 2; ++nt2) {
        const int r = wn * 32 + nt2 * 16 + lr8;
        offB[nt2] = (uint32_t)(r * 32 + ((lchm ^ ((r >> 2) & 1)) << 4));
    }

    int acc1[4][4][4], acc2[4][4][4];
#pragma unroll
    for (int mt = 0; mt < 4; ++mt)
#pragma unroll
        for (int nt = 0; nt < 4; ++nt)
#pragma unroll
            for (int c = 0; c < 4; ++c) { acc1[mt][nt][c] = 0; acc2[mt][nt][c] = 0; }

    // ---- 3-stage pipeline, one barrier per iteration ----
    load_stage(0, 0); CP_COMMIT();
    load_stage(1, 1); CP_COMMIT();

    for (int kt = 0; kt < NKT; ++kt) {
        CP_WAIT1();
        __syncthreads();

        if (kt + 2 < NKT) load_stage(kt + 2, (kt + 2) % NSTAGE);
        CP_COMMIT();

        const uint32_t sbase = db + (kt % NSTAGE) * STAGE_BYTES;

        uint32_t b1f[2][4], b0f[2][4], a[4][4];
#pragma unroll
        for (int nt2 = 0; nt2 < 2; ++nt2) {
            LDM4(b1f[nt2], sbase + 8192 + offB[nt2]);
            LDM4(b0f[nt2], sbase + 12288 + offB[nt2]);
        }
        // a1 limb: P11 += a1*b1 ; P10 += a1*b0
#pragma unroll
        for (int mt = 0; mt < 4; ++mt)
            LDM4(a[mt], sbase + offA[mt]);
#pragma unroll
        for (int mt = 0; mt < 4; ++mt)
#pragma unroll
            for (int nt = 0; nt < 4; ++nt) {
                const int q = nt >> 1, o = nt & 1;      // o=0 -> regs {0,2}, o=1 -> {1,3}
                IMMA(acc1[mt][nt], a[mt], b1f[q][o], b1f[q][o + 2]);
                IMMA(acc2[mt][nt], a[mt], b0f[q][o], b0f[q][o + 2]);
            }
        // a0 limb: P10 += a0*b1
#pragma unroll
        for (int mt = 0; mt < 4; ++mt)
            LDM4(a[mt], sbase + 4096 + offA[mt]);
#pragma unroll
        for (int mt = 0; mt < 4; ++mt)
#pragma unroll
            for (int nt = 0; nt < 4; ++nt) {
                const int q = nt >> 1, o = nt & 1;
                IMMA(acc2[mt][nt], a[mt], b1f[q][o], b1f[q][o + 2]);
            }
    }

    // ---- epilogue: scale + bias + fp32 store to g_C ----
    const float k1 = SX * SW * 16384.0f;
    const float k2 = SX * SW * 128.0f;
#pragma unroll
    for (int mt = 0; mt < 4; ++mt) {
        const int r0 = m0 + wm * 64 + mt * 16 + (l >> 2);
#pragma unroll
        for (int nt = 0; nt < 4; ++nt) {
            const int col = n0 + wn * 32 + nt * 8 + (l & 3) * 2;
            const float2 bb = *(const float2*)(g_bias + col);
            float2 o;
            o.x = fmaf(k1, (float)acc1[mt][nt][0], fmaf(k2, (float)acc2[mt][nt][0], bb.x));
            o.y = fmaf(k1, (float)acc1[mt][nt][1], fmaf(k2, (float)acc2[mt][nt][1], bb.y));
            *(float2*)(g_C + (size_t)r0 * CN + col) = o;
            o.x = fmaf(k1, (float)acc1[mt][nt][2], fmaf(k2, (float)acc2[mt][nt][2], bb.x));
            o.y = fmaf(k1, (float)acc1[mt][nt][3], fmaf(k2, (float)acc2[mt][nt][3], bb.y));
            *(float2*)(g_C + (size_t)(r0 + 8) * CN + col) = o;
        }
    }
}

// ---------------------------------------------------------------------------
// Partial column sums of V (uniform fallback)
// ---------------------------------------------------------------------------
__global__ void vsum_kernel()
{
    const int col = (blockIdx.x & 7) * 128 + threadIdx.x;
    const int b   = blockIdx.x >> 3;
    const int s0  = blockIdx.y * 256;
    const float* base = g_C + (size_t)(b * S_ + s0) * CN + 2048 + col;
    float s = 0.0f;
#pragma unroll 8
    for (int k = 0; k < 256; ++k) s += base[(size_t)k * CN];
    g_vsum[blockIdx.y * (B_ * ODIM) + b * ODIM + col] = s;
}

// ---------------------------------------------------------------------------
// Local attention (one warp per row) — unchanged (passed R2/R4/R5/R6)
// ---------------------------------------------------------------------------
__global__ void __launch_bounds__(256) attn_kernel(
    const float* __restrict__ m_feats, const int* __restrict__ mask,
    float* __restrict__ out_um, float* __restrict__ out_w)
{
    __shared__ float sk[8][64];
    __shared__ float sw[8][16];

    const int wid = threadIdx.x >> 5;
    const int l   = threadIdx.x & 31;
    const int row = blockIdx.x * 8 + wid;
    const int b   = row >> 14;
    const int h   = (row >> 10) & 15;
    const int i   = row & 1023;
    const int lo  = i - 7;

    {
        const float* kp = g_C + (size_t)(b * S_ + i) * CN + h * HD_;
        float2 kv = *(const float2*)(kp + 2 * l);
        sk[wid][2 * l]     = kv.x;
        sk[wid][2 * l + 1] = kv.y;
    }
    __syncwarp();

    float score = -FLT_MAX;
    if (l < 15) {
        const int j = lo + l;
        if (j >= 0 && j < S_ && mask[b * S_ + j] != 0) {
            const float* q = g_C + (size_t)(b * S_ + j) * CN + 1024 + h * HD_;
            float dot = 0.0f;
#pragma unroll
            for (int d = 0; d < HD_; d += 4) {
                float4 qq = *(const float4*)(q + d);
                dot += sk[wid][d]     * qq.x + sk[wid][d + 1] * qq.y
                     + sk[wid][d + 2] * qq.z + sk[wid][d + 3] * qq.w;
            }
            score = dot * 0.125f;
        }
    }

    float m = score;
#pragma unroll
    for (int o = 16; o; o >>= 1) m = fmaxf(m, __shfl_xor_sync(0xFFFFFFFFu, m, o));
    const bool uniform = (m == -FLT_MAX);

    float w = 0.0f;
    if (!uniform) {
        float e = (score != -FLT_MAX) ? expf(score - m) : 0.0f;
        float s = e;
#pragma unroll
        for (int o = 16; o; o >>= 1) s += __shfl_xor_sync(0xFFFFFFFFu, s, o);
        w = e / s;
    }
    if (l < 16) sw[wid][l] = (l < 15) ? w : 0.0f;
    __syncwarp();

    float r0 = 0.0f, r1 = 0.0f;
    if (!uniform) {
#pragma unroll
        for (int jj = 0; jj < 15; ++jj) {
            const float wv = sw[wid][jj];
            if (wv != 0.0f) {
                const float* v = g_C + (size_t)(b * S_ + lo + jj) * CN + 2048 + h * HD_;
                float2 vv = *(const float2*)(v + 2 * l);
                r0 = fmaf(wv, vv.x, r0);
                r1 = fmaf(wv, vv.y, r1);
            }
        }
    } else {
        const int c = h * HD_ + 2 * l;
        float s0 = 0.0f, s1 = 0.0f;
#pragma unroll
        for (int p = 0; p < 4; ++p) {
            s0 += g_vsum[p * (B_ * ODIM) + b * ODIM + c];
            s1 += g_vsum[p * (B_ * ODIM) + b * ODIM + c + 1];
        }
        r0 = s0 * (1.0f / 1024.0f);
        r1 = s1 * (1.0f / 1024.0f);
    }

    {
        const size_t uoff = (size_t)(b * S_ + i) * ODIM + h * HD_ + 2 * l;
        float2 mf = *(const float2*)(m_feats + uoff);
        float2 o;
        o.x = mf.x + r0;
        o.y = mf.y + r1;
        *(float2*)(out_um + uoff) = o;
    }

    {
        float* wr = out_w + (size_t)row * S_;
        const float uval = 1.0f / 1024.0f;
#pragma unroll
        for (int tt = 0; tt < 8; ++tt) {
            const int col = tt * 128 + l * 4;
            float4 o;
            if (uniform) {
                o = make_float4(uval, uval, uval, uval);
            } else {
                o.x = ((unsigned)(col     - lo) < 15u) ? sw[wid][col     - lo] : 0.0f;
                o.y = ((unsigned)(col + 1 - lo) < 15u) ? sw[wid][col + 1 - lo] : 0.0f;
                o.z = ((unsigned)(col + 2 - lo) < 15u) ? sw[wid][col + 2 - lo] : 0.0f;
                o.w = ((unsigned)(col + 3 - lo) < 15u) ? sw[wid][col + 3 - lo] : 0.0f;
            }
            *(float4*)(wr + col) = o;
        }
    }
}

// ---------------------------------------------------------------------------
extern "C" void kernel_launch(void* const* d_in, const int* in_sizes, int n_in,
                              void* d_out, int out_size)
{
    (void)in_sizes; (void)n_in; (void)out_size;
    const float* m_feats = (const float*)d_in[0];
    const int*   mask    = (const int*)  d_in[1];
    const float* Wc      = (const float*)d_in[2];
    const float* bc      = (const float*)d_in[3];
    const float* Wv      = (const float*)d_in[4];
    const float* bv      = (const float*)d_in[5];

    float* out_um = (float*)d_out;
    float* out_w  = out_um + (size_t)B_ * S_ * ODIM;

    cudaFuncSetAttribute(mma_kernel, cudaFuncAttributeMaxDynamicSharedMemorySize, SMEM_ALLOC);

    xq_kernel<<<(M_ * IDIM) / 1024, 256>>>(m_feats, bc, bv);
    wq_kernel<<<dim3(CN / 32, IDIM / 32), 256>>>(Wc, Wv);
    mma_kernel<<<dim3(CN / TN, M_ / TM), 256, SMEM_ALLOC>>>();
    vsum_kernel<<<dim3(64, 4), 128>>>();
    attn_kernel<<<(B_ * H_ * S_) / 8, 256>>>(m_feats, mask, out_um, out_w);
}